// round 12
// baseline (speedup 1.0000x reference)
#include <cuda_runtime.h>
#include <cstdint>
#include <cstddef>

// Problem constants
#define BB 16
#define CC 256
#define HH 64
#define WW 64
#define HW (HH*WW)
#define DD 4          // max displacement
#define PP 9          // patch = 2d+1

// Tiling
#define TI 4          // rows per block tile
#define KC 8          // channels per staged chunk
#define NCP 4         // channel PAIRS per chunk (float2 slots)
#define NCHUNK (CC/KC)
#define XSLOT 66      // f2 slots per x row (64 + 2 pad): LDS.128 residues r+4qq -> CF
#define YR (TI + 2*DD)   // 12 y rows
#define YSLOT 74      // f2 slots per y row (4 halo + 64 + 4 halo + 2 pad): 5ry+4qq -> CF

#define NTH 576       // 18 warps: di = w>>1 (0..8), sub = w&1
#define NBUF 3

#define XSZ2 (NCP*TI*XSLOT)    // 1056 f2 slots (8448 B)
#define YSZ2 (NCP*YR*YSLOT)    // 3552 f2 slots (28416 B)
#define BUF2 (XSZ2+YSZ2)       // 4608 f2 slots (36864 B)
#define SMEM_BYTES (NBUF*BUF2*8)   // 110592 B

// packed fp32x2 FMA: c += a*b (elementwise) — Blackwell FFMA2, proven in R5
__device__ __forceinline__ void ffma2(float2& c, const float2& a, const float2& b) {
    unsigned long long&       cc = reinterpret_cast<unsigned long long&>(c);
    const unsigned long long& aa = reinterpret_cast<const unsigned long long&>(a);
    const unsigned long long& bb = reinterpret_cast<const unsigned long long&>(b);
    asm("fma.rn.f32x2 %0, %1, %2, %0;" : "+l"(cc) : "l"(aa), "l"(bb));
}

// Stage one 8-channel chunk, channel-pair interleaved.
// Slot (cp, pos, j) holds {v[c0+2cp][pos][j], v[c0+2cp+1][pos][j]}.
__device__ __forceinline__ void stage_chunk(float2* sb,
                                            const float* __restrict__ xb,
                                            const float* __restrict__ yb,
                                            int c0, int i0, int tid, int vmask)
{
    // x: 512 jobs: j2 = idx&31 (cols 2j2,2j2+1), r = (idx>>5)&3, cp = idx>>7
    #pragma unroll 1
    for (int idx = tid; idx < NCP * TI * 32; idx += NTH) {
        int j2 = idx & 31;
        int r  = (idx >> 5) & 3;
        int cp = idx >> 7;
        const float* g0 = xb + (size_t)(c0 + 2 * cp) * HW + (i0 + r) * WW + 2 * j2;
        float2 a = *reinterpret_cast<const float2*>(g0);
        float2 bv = *reinterpret_cast<const float2*>(g0 + HW);
        float4 v = make_float4(a.x, bv.x, a.y, bv.y);
        *reinterpret_cast<float4*>(sb + cp * (TI * XSLOT) + r * XSLOT + 2 * j2) = v;
    }
    // y: 1536 jobs: j2 = idx&31, t = idx>>5: cp = t&3, q = t>>2
    #pragma unroll 1
    for (int idx = tid; idx < NCP * YR * 32; idx += NTH) {
        int j2 = idx & 31;
        int t  = idx >> 5;
        int cp = t & 3;
        int q  = t >> 2;
        if ((vmask >> q) & 1) {
            int gi = i0 + q - DD;
            const float* g0 = yb + (size_t)(c0 + 2 * cp) * HW + gi * WW + 2 * j2;
            float2 a = *reinterpret_cast<const float2*>(g0);
            float2 bv = *reinterpret_cast<const float2*>(g0 + HW);
            float4 v = make_float4(a.x, bv.x, a.y, bv.y);
            *reinterpret_cast<float4*>(sb + XSZ2 + cp * (YR * YSLOT) + q * YSLOT
                                       + 4 + 2 * j2) = v;
        }
    }
}

// Compute: 4 cols x 9 dj, channel-paired: 36 FFMA2 per cpair, 8 LDS.128 per cpair.
__device__ __forceinline__ void compute_chunk(const float2* sb, float2 acc2[4][PP],
                                              int r, int ry, int jc)
{
    #pragma unroll
    for (int cp = 0; cp < NCP; ++cp) {
        const float4* X = reinterpret_cast<const float4*>(
            sb + cp * (TI * XSLOT) + r * XSLOT + jc);
        const float4* Y = reinterpret_cast<const float4*>(
            sb + XSZ2 + cp * (YR * YSLOT) + ry * YSLOT + jc);

        float4 xa = X[0], xb4 = X[1];
        float2 xp[4] = { {xa.x, xa.y}, {xa.z, xa.w}, {xb4.x, xb4.y}, {xb4.z, xb4.w} };

        float2 yp[12];
        #pragma unroll
        for (int m = 0; m < 6; ++m) {
            float4 v = Y[m];
            yp[2 * m]     = make_float2(v.x, v.y);
            yp[2 * m + 1] = make_float2(v.z, v.w);
        }

        #pragma unroll
        for (int k = 0; k < 4; ++k)
            #pragma unroll
            for (int d = 0; d < PP; ++d)
                ffma2(acc2[k][d], xp[k], yp[k + d]);
    }
}

__global__ __launch_bounds__(NTH, 1)
void corr_kernel(const float* __restrict__ x,
                 const float* __restrict__ y,
                 float* __restrict__ out)
{
    extern __shared__ float2 smem[];   // [NBUF][BUF2]

    const int bx   = blockIdx.x;
    const int b    = bx >> 4;
    const int i0   = (bx & 15) * TI;
    const int tid  = threadIdx.x;
    const int w    = tid >> 5;
    const int di   = w >> 1;               // 0..8
    const int sub  = w & 1;
    const int lane = tid & 31;
    const int r    = lane & 3;             // local row
    const int qq   = lane >> 2;            // 0..7
    const int jc   = (2 * qq + sub) * 4;   // column base (interleaved 4-col groups)
    const int ry   = r + di;               // y row in padded tile

    const float* xb = x + (size_t)b * CC * HW;
    const float* yb = y + (size_t)b * CC * HW;

    // Valid-row mask for the y tile (rows i0-4 .. i0+7)
    int vmask = 0;
    #pragma unroll
    for (int q = 0; q < YR; ++q) {
        int gi = i0 + q - DD;
        if (gi >= 0 && gi < HH) vmask |= (1 << q);
    }

    // Zero y regions of all buffers once; halo slots / invalid rows never rewritten.
    {
        const float2 z = make_float2(0.f, 0.f);
        #pragma unroll
        for (int nb = 0; nb < NBUF; ++nb) {
            float2* yz = smem + nb * BUF2 + XSZ2;
            for (int idx = tid; idx < YSZ2; idx += NTH) yz[idx] = z;
        }
    }
    __syncthreads();

    float2 acc2[4][PP];
    #pragma unroll
    for (int k = 0; k < 4; ++k)
        #pragma unroll
        for (int d = 0; d < PP; ++d)
            acc2[k][d] = make_float2(0.f, 0.f);

    // Prime two chunks
    stage_chunk(smem + 0 * BUF2, xb, yb, 0, i0, tid, vmask);
    __syncthreads();
    stage_chunk(smem + 1 * BUF2, xb, yb, KC, i0, tid, vmask);

    // sync -> compute(k) -> stage(k+2): stage writes buf (k-1)%3; every thread
    // is past sync(k), which follows its compute(k-1) reads. The next sync
    // drains the STS of stage(k+1) before compute(k+1) reads it.
    int cur = 0, nxt = 2;
    for (int k = 0; k < NCHUNK; ++k) {
        __syncthreads();
        compute_chunk(smem + cur * BUF2, acc2, r, ry, jc);
        if (k + 2 < NCHUNK) {
            stage_chunk(smem + nxt * BUF2, xb, yb, (k + 2) * KC, i0, tid, vmask);
        }
        cur = (cur + 1 == NBUF) ? 0 : cur + 1;
        nxt = (nxt + 1 == NBUF) ? 0 : nxt + 1;
    }

    // Write out: out[b, di*9+d, i0+r, jc..jc+3]; value = sum of both channel lanes.
    const float scale = 1.0f / (float)CC;
    #pragma unroll
    for (int d = 0; d < PP; ++d) {
        int ch = di * PP + d;
        float* o = out + (((size_t)b * (PP * PP) + ch) * HH + (i0 + r)) * WW + jc;
        float4 v;
        v.x = (acc2[0][d].x + acc2[0][d].y) * scale;
        v.y = (acc2[1][d].x + acc2[1][d].y) * scale;
        v.z = (acc2[2][d].x + acc2[2][d].y) * scale;
        v.w = (acc2[3][d].x + acc2[3][d].y) * scale;
        reinterpret_cast<float4*>(o)[0] = v;
    }
}

extern "C" void kernel_launch(void* const* d_in, const int* in_sizes, int n_in,
                              void* d_out, int out_size)
{
    const float* x = (const float*)d_in[0];
    const float* y = (const float*)d_in[1];
    float* out = (float*)d_out;
    (void)in_sizes; (void)n_in; (void)out_size;

    cudaFuncSetAttribute(corr_kernel,
                         cudaFuncAttributeMaxDynamicSharedMemorySize, SMEM_BYTES);

    dim3 grid(BB * (HH / TI));   // 256 blocks
    dim3 block(NTH);             // 18 warps
    corr_kernel<<<grid, block, SMEM_BYTES>>>(x, y, out);
}

// round 13
// speedup vs baseline: 1.6965x; 1.6965x over previous
#include <cuda_runtime.h>
#include <cstdint>
#include <cstddef>

// Problem constants
#define BB 16
#define CC 256
#define HH 64
#define WW 64
#define HW (HH*WW)
#define DD 4          // max displacement
#define PP 9          // patch = 2d+1

// Tiling
#define TI 4          // rows per block tile
#define KC 8          // channels per staged chunk
#define NCHUNK (CC/KC)
#define XS 66         // x smem row stride (floats); LDS.64 residues conflict-free (proven)
#define YR (TI + 2*DD)   // 12 y rows per tile
#define YS 76         // y smem row stride (floats) = 19 f4; LDS.128 residues 3r+2q -> CF

#define NTH 288       // 9 warps; warp w == displacement row di
#define NBUF 3        // triple buffer -> single barrier per chunk

#define XSZ (KC*TI*XS)     // 2112 floats
#define YSZ (KC*YR*YS)     // 7296 floats
#define BUFSZ (XSZ+YSZ)    // 9408 floats = 37632 B
#define SMEM_BYTES (NBUF*BUFSZ*4)   // 112896 B; x2 blocks/SM = 225.8 KB <= 228 KB

__device__ __forceinline__ uint32_t s2u(const void* p) {
    return (uint32_t)__cvta_generic_to_shared(p);
}
__device__ __forceinline__ void cpa8(uint32_t s, const float* g) {
    asm volatile("cp.async.ca.shared.global [%0], [%1], 8;\n" :: "r"(s), "l"(g));
}
__device__ __forceinline__ void cpa16(uint32_t s, const float* g) {
    asm volatile("cp.async.cg.shared.global [%0], [%1], 16;\n" :: "r"(s), "l"(g));
}
__device__ __forceinline__ void cp_commit() {
    asm volatile("cp.async.commit_group;\n");
}

// Stage one 8-channel chunk into buffer sb. Shift/mask index math only.
__device__ __forceinline__ void stage_chunk(float* sb,
                                            const float* __restrict__ xb,
                                            const float* __restrict__ yb,
                                            int c0, int i0, int tid, int vmask)
{
    // x: KC*TI*32 = 1024 float2 jobs (8B; XS=66 keeps 8B alignment only)
    for (int idx = tid; idx < KC * TI * 32; idx += NTH) {
        int c    = idx >> 7;
        int rr   = (idx >> 5) & 3;
        int col2 = idx & 31;
        uint32_t s = s2u(sb + c * (TI * XS) + rr * XS + col2 * 2);
        cpa8(s, xb + (size_t)(c0 + c) * HW + (i0 + rr) * WW + col2 * 2);
    }
    // y: KC*YR*16 = 1536 float4 jobs (16B, L1-bypass). Data floats 4..67 of
    // padded row => f4 slot 1 + j4. Row base q*YS: q*76*4 B = q*304 B, 16B ok.
    for (int idx = tid; idx < KC * YR * 16; idx += NTH) {
        int j4  = idx & 15;
        int row = idx >> 4;
        int c   = row & 7;
        int q   = row >> 3;
        if ((vmask >> q) & 1) {
            int gi = i0 + q - DD;
            uint32_t s = s2u(sb + XSZ + c * (YR * YS) + q * YS + 4 + j4 * 4);
            cpa16(s, yb + (size_t)(c0 + c) * HW + gi * WW + j4 * 4);
        }
    }
}

// Compute: 8 columns x 9 dj per thread; 4 LDS.64 (x) + 4 LDS.128 (y), 72 FFMA.
__device__ __forceinline__ void compute_chunk(const float* sb, float acc[8][PP],
                                              int r, int ry, int jseg)
{
    #pragma unroll
    for (int c = 0; c < KC; ++c) {
        const float2* xr2 = reinterpret_cast<const float2*>(
            sb + c * (TI * XS) + r * XS + jseg);
        const float4* yr4 = reinterpret_cast<const float4*>(
            sb + XSZ + c * (YR * YS) + ry * YS + jseg);

        float xv[8], yv[16];
        #pragma unroll
        for (int m = 0; m < 4; ++m) {
            float2 v = xr2[m];
            xv[2 * m] = v.x; xv[2 * m + 1] = v.y;
        }
        #pragma unroll
        for (int m = 0; m < 4; ++m) {
            float4 v = yr4[m];
            yv[4 * m]     = v.x; yv[4 * m + 1] = v.y;
            yv[4 * m + 2] = v.z; yv[4 * m + 3] = v.w;
        }
        #pragma unroll
        for (int k = 0; k < 8; ++k)
            #pragma unroll
            for (int d = 0; d < PP; ++d)
                acc[k][d] += xv[k] * yv[k + d];
    }
}

__global__ __launch_bounds__(NTH, 2)
void corr_kernel(const float* __restrict__ x,
                 const float* __restrict__ y,
                 float* __restrict__ out)
{
    extern __shared__ float smem[];   // [NBUF][BUFSZ]

    const int bx   = blockIdx.x;
    const int b    = bx >> 4;
    const int i0   = (bx & 15) * TI;
    const int tid  = threadIdx.x;
    const int di   = tid >> 5;
    const int lane = tid & 31;
    const int r    = lane & 3;
    const int ry   = r + di;              // y row in padded tile
    const int jseg = (lane >> 2) * 8;     // 32B-aligned within row

    const float* xb = x + (size_t)b * CC * HW;
    const float* yb = y + (size_t)b * CC * HW;

    // Valid-row mask for the y tile (rows i0-4 .. i0+7)
    int vmask = 0;
    #pragma unroll
    for (int q = 0; q < YR; ++q) {
        int gi = i0 + q - DD;
        if (gi >= 0 && gi < HH) vmask |= (1 << q);
    }

    // Zero the y regions of all buffers once; halo slots / invalid rows are
    // never rewritten by staging.
    {
        const float4 z = make_float4(0.f, 0.f, 0.f, 0.f);
        #pragma unroll
        for (int nb = 0; nb < NBUF; ++nb) {
            float4* yz = reinterpret_cast<float4*>(smem + nb * BUFSZ + XSZ);
            for (int idx = tid; idx < YSZ / 4; idx += NTH) yz[idx] = z;
        }
    }
    __syncthreads();

    float acc[8][PP];
    #pragma unroll
    for (int k = 0; k < 8; ++k)
        #pragma unroll
        for (int d = 0; d < PP; ++d)
            acc[k][d] = 0.0f;

    // Prime two chunks
    stage_chunk(smem + 0 * BUFSZ, xb, yb, 0, i0, tid, vmask);
    cp_commit();
    stage_chunk(smem + 1 * BUFSZ, xb, yb, KC, i0, tid, vmask);
    cp_commit();

    // wait(k) -> sync -> compute(k) -> stage(k+2): stage writes buf (k-1)%3;
    // every thread is past sync(k), which follows its compute(k-1) reads of
    // that buffer. One barrier per chunk. (Ordering proven in R5/R8.)
    int cur = 0, nxt = 2;
    for (int k = 0; k < NCHUNK; ++k) {
        if (k + 1 < NCHUNK) {
            asm volatile("cp.async.wait_group 1;\n");   // chunk k's group done
        } else {
            asm volatile("cp.async.wait_group 0;\n");
        }
        __syncthreads();
        compute_chunk(smem + cur * BUFSZ, acc, r, ry, jseg);
        if (k + 2 < NCHUNK) {
            stage_chunk(smem + nxt * BUFSZ, xb, yb, (k + 2) * KC, i0, tid, vmask);
            cp_commit();
        }
        cur = (cur + 1 == NBUF) ? 0 : cur + 1;
        nxt = (nxt + 1 == NBUF) ? 0 : nxt + 1;
    }

    // Write out: out[b, di*9+d, i0+r, jseg..jseg+7]
    const float scale = 1.0f / (float)CC;
    #pragma unroll
    for (int d = 0; d < PP; ++d) {
        int ch = di * PP + d;
        float* o = out + (((size_t)b * (PP * PP) + ch) * HH + (i0 + r)) * WW + jseg;
        float4 v0, v1;
        v0.x = acc[0][d] * scale; v0.y = acc[1][d] * scale;
        v0.z = acc[2][d] * scale; v0.w = acc[3][d] * scale;
        v1.x = acc[4][d] * scale; v1.y = acc[5][d] * scale;
        v1.z = acc[6][d] * scale; v1.w = acc[7][d] * scale;
        reinterpret_cast<float4*>(o)[0] = v0;
        reinterpret_cast<float4*>(o)[1] = v1;
    }
}

extern "C" void kernel_launch(void* const* d_in, const int* in_sizes, int n_in,
                              void* d_out, int out_size)
{
    const float* x = (const float*)d_in[0];
    const float* y = (const float*)d_in[1];
    float* out = (float*)d_out;
    (void)in_sizes; (void)n_in; (void)out_size;

    cudaFuncSetAttribute(corr_kernel,
                         cudaFuncAttributeMaxDynamicSharedMemorySize, SMEM_BYTES);

    dim3 grid(BB * (HH / TI));   // 256 blocks
    dim3 block(NTH);             // 9 warps
    corr_kernel<<<grid, block, SMEM_BYTES>>>(x, y, out);
}